// round 10
// baseline (speedup 1.0000x reference)
#include <cuda_runtime.h>
#include <math.h>

typedef unsigned long long u64;
typedef unsigned int u32;

// ---------------- problem constants ----------------
#define L0H 200
#define L0W 336
#define L1H 100
#define L1W 168
#define HW0 (L0H*L0W)      // 67200
#define HW1 (L1H*L1W)      // 16800
#define N0 (3*HW0)         // 201600
#define N1 (3*HW1)         // 50400
#define NT (N0+N1)         // 252000
// output regions (floats), tuple order:
// anchors (NT,4) | obj (1,NT) | f_scores (2000) | f_props (2000,4) | deltas (1,NT,4)
#define R_OBJ   (NT*4)          // 1008000
#define R_FS    (R_OBJ+NT)      // 1260000
#define R_FP    (R_FS+2000)     // 1262000
#define R_DELTA (R_FP+8000)     // 1270000

// ---------------- device scratch (static, no runtime alloc) ----------------
__device__ float  g_cw[2][2304][12];   // folded reg weights (fp32) [level][i*9+tap][o]
__device__ double g_cwd[2][2304][3];   // folded det weights (fp64)
__device__ float  g_cb[2][12];         // folded reg bias
__device__ double g_cbd[2][3];         // folded det bias (fp64)
__device__ float4 g_props[NT];         // decoded+clipped proposals
__device__ u64    g_keys[NT];          // (score_bits<<32)|(0xFFFFFFFF-idx): unique, stable tiebreak
__device__ u64    g_selkeys[2][2048];
__device__ float4 g_selbox[2][2048];
__device__ float  g_selscore[2][2048];
__device__ u64    g_masks[2][2000*32]; // NMS suppression bitmatrix (row i: bits j>i with iou>0.7)
__device__ u64    g_keepw[2][32];
__device__ u64    g_prefix[2];
__device__ int    g_krem[2];
__device__ int    g_selcnt[2];
__device__ u32    g_hist[2][256];

// ---------------- f32x2 helpers ----------------
__device__ __forceinline__ u64 pk2(float lo, float hi){
    u64 v; asm("mov.b64 %0,{%1,%2};" : "=l"(v) : "f"(lo), "f"(hi)); return v;
}
__device__ __forceinline__ void upk2(u64 v, float& lo, float& hi){
    asm("mov.b64 {%0,%1},%2;" : "=f"(lo), "=f"(hi) : "l"(v));
}
__device__ __forceinline__ u64 ff2(u64 a, u64 b, u64 c){
    u64 d; asm("fma.rn.f32x2 %0,%1,%2,%3;" : "=l"(d) : "l"(a), "l"(b), "l"(c)); return d;
}

// ---------------- per-call init ----------------
__global__ void k_init(float* __restrict__ out){
    int t = blockIdx.x*blockDim.x + threadIdx.x;
    if (t < 2){ g_prefix[t] = 0ull; g_krem[t] = 2000; g_selcnt[t] = 0; }
    if (t < 512) g_hist[t>>8][t&255] = 0u;
    if (t < 96){ int lv = t/48; g_selkeys[lv][2000 + (t%48)] = 0ull; }
    if (t < 10000) out[R_FS + t] = 0.f;   // zero f_scores + f_props regions
}

// ---------------- fold weights: cw[lv][l][o] = sum_c head_w[o,c]*conv_w[c][l] ----------------
// det channels folded in fp64 (ranking precision), reg channels in fp32.
__global__ void __launch_bounds__(256) k_fold(const float* __restrict__ w30,
                                              const float* __restrict__ w31,
                                              const float* __restrict__ detw,
                                              const float* __restrict__ regw){
    __shared__ float  hwr[12*256];
    __shared__ double hwd[3*256];
    int tid = threadIdx.x;
    for (int s = tid; s < 12*256; s += 256){
        int o = s >> 8, c = s & 255;
        hwr[s] = regw[o*256 + c];
    }
    for (int s = tid; s < 3*256; s += 256){
        int o = s >> 8, c = s & 255;
        hwd[s] = (double)detw[o*256 + c];
    }
    __syncthreads();
    int lin = blockIdx.x*256 + tid;          // 0..4607
    int lv  = (lin >= 2304);
    int l   = lv ? (lin - 2304) : lin;       // 0..2303 = i*9 + tap
    const float* w3 = lv ? w31 : w30;
    float  fa[12];
    double da[3];
#pragma unroll
    for (int o = 0; o < 12; o++) fa[o] = 0.f;
#pragma unroll
    for (int a = 0; a < 3; a++) da[a] = 0.0;
    for (int c = 0; c < 256; c++){
        float x = w3[c*2304 + l];
        double xd = (double)x;
#pragma unroll
        for (int a = 0; a < 3; a++) da[a] += hwd[(a<<8) + c] * xd;
#pragma unroll
        for (int o = 0; o < 12; o++) fa[o] += hwr[(o<<8) + c] * x;
    }
#pragma unroll
    for (int o = 0; o < 12; o++) g_cw[lv][l][o] = fa[o];
#pragma unroll
    for (int a = 0; a < 3; a++) g_cwd[lv][l][a] = da[a];
}

__global__ void k_foldb(const float* __restrict__ cb0, const float* __restrict__ cb1,
                        const float* __restrict__ detw, const float* __restrict__ detb,
                        const float* __restrict__ regw, const float* __restrict__ regb){
    int t = threadIdx.x;
    if (t >= 32) return;
    int lv = t / 16, o = t % 16;
    const float* cb = lv ? cb1 : cb0;
    if (o < 3){
        double s = (double)detb[o];
        for (int c = 0; c < 256; c++) s += (double)detw[o*256 + c] * (double)cb[c];
        g_cbd[lv][o] = s;
    } else if (o < 15){
        int ro = o - 3;
        float s = regb[ro];
        for (int c = 0; c < 256; c++) s += regw[ro*256 + c] * cb[c];
        g_cb[lv][ro] = s;
    }
}

// ---------------- fused folded conv3x3 + sigmoid + anchors + decode ----------------
// tile 16H x 32W, 128 threads, 4 px/thread.
// det channels: fp64 accumulation (exact ranking). reg channels: f32x2 packed.
__global__ void __launch_bounds__(128) k_conv(const float* __restrict__ x0,
                                              const float* __restrict__ x1,
                                              float* __restrict__ out){
    __shared__ float  xs[8][18][34];
    __shared__ u64    ws_reg[8*9*12];
    __shared__ double ws_det[8*9*3];
    int b = blockIdx.x;
    int lv, H, W, lvbase, tx, ty; const float* xin;
    if (b < 143){ lv = 0; tx = b % 11; ty = b / 11; H = L0H; W = L0W; xin = x0; lvbase = 0;  }
    else { int c = b - 143; lv = 1; tx = c % 6; ty = c / 6; H = L1H; W = L1W; xin = x1; lvbase = N0; }
    int HW = H * W;
    int X0 = tx * 32, Y0 = ty * 16;
    int tid = threadIdx.x;
    int wcol = tid & 31, r0 = (tid >> 5) * 4;

    u64 racc[24];
    double dacc[12];
#pragma unroll
    for (int o = 0; o < 12; o++){
        float bb = g_cb[lv][o];
        u64 p = pk2(bb, bb);
        racc[2*o] = p; racc[2*o+1] = p;
    }
#pragma unroll
    for (int a = 0; a < 3; a++){
        double bd = g_cbd[lv][a];
#pragma unroll
        for (int j = 0; j < 4; j++) dacc[a*4+j] = bd;
    }

    for (int cc = 0; cc < 256; cc += 8){
        __syncthreads();
        for (int s = tid; s < 8*18*34; s += 128){
            int ic = s / 612; int rm = s - ic*612; int r = rm / 34; int c2 = rm - r*34;
            int gy = Y0 - 1 + r, gx = X0 - 1 + c2;
            float v = 0.f;
            if ((unsigned)gy < (unsigned)H && (unsigned)gx < (unsigned)W)
                v = xin[(cc+ic)*HW + gy*W + gx];
            xs[ic][r][c2] = v;
        }
        for (int s = tid; s < 864; s += 128){
            int ic = s / 108; int rm = s - ic*108; int tap = rm / 12; int o = rm - tap*12;
            float w = g_cw[lv][(cc+ic)*9 + tap][o];
            ws_reg[(ic*9 + tap)*12 + o] = pk2(w, w);
        }
        for (int s = tid; s < 216; s += 128){
            int ic = s / 27; int rm = s - ic*27; int tap = rm / 3; int a = rm - tap*3;
            ws_det[(ic*9 + tap)*3 + a] = g_cwd[lv][(cc+ic)*9 + tap][a];
        }
        __syncthreads();
#pragma unroll 1
        for (int ic = 0; ic < 8; ic++){
            float xc[3][6];
#pragma unroll
            for (int kx = 0; kx < 3; kx++)
#pragma unroll
                for (int j = 0; j < 6; j++)
                    xc[kx][j] = xs[ic][r0 + j][wcol + kx];
#pragma unroll
            for (int kx = 0; kx < 3; kx++){
                double xd[6];
#pragma unroll
                for (int j = 0; j < 6; j++) xd[j] = (double)xc[kx][j];
#pragma unroll
                for (int ky = 0; ky < 3; ky++){
                    u64 xv0 = pk2(xc[kx][ky],   xc[kx][ky+1]);
                    u64 xv1 = pk2(xc[kx][ky+2], xc[kx][ky+3]);
                    const u64* wr = &ws_reg[(ic*9 + ky*3 + kx)*12];
#pragma unroll
                    for (int o = 0; o < 12; o++){
                        u64 wv = wr[o];
                        racc[2*o]   = ff2(wv, xv0, racc[2*o]);
                        racc[2*o+1] = ff2(wv, xv1, racc[2*o+1]);
                    }
                    const double* wd = &ws_det[(ic*9 + ky*3 + kx)*3];
#pragma unroll
                    for (int a = 0; a < 3; a++){
                        double w = wd[a];
#pragma unroll
                        for (int j = 0; j < 4; j++)
                            dacc[a*4+j] += w * xd[ky + j];
                    }
                }
            }
        }
    }

    // epilogue: sigmoid, anchors (clipped), deltas, decode (with ref's x/y-center swap), clip
    float scale = lv ? 8.f : 4.f;
    float sz    = lv ? 64.f : 32.f;
#pragma unroll
    for (int p = 0; p < 4; p++){
        int gy = Y0 + r0 + p, gx = X0 + wcol;
        if (gy >= H || gx >= W) continue;
        float rv[12];
#pragma unroll
        for (int o = 0; o < 12; o++){
            float lo, hi; upk2(racc[2*o + (p>>1)], lo, hi);
            rv[o] = (p & 1) ? hi : lo;
        }
        int pix = gy*W + gx;
        float cx = (gx + 0.5f) * scale, cy = (gy + 0.5f) * scale;
#pragma unroll
        for (int a = 0; a < 3; a++){
            float lg = (float)dacc[a*4 + p];           // exact fp64 logit -> fp32 (ref quantization)
            float score = 1.f / (1.f + expf(-lg));
            int idx  = a*HW + pix;
            int gidx = lvbase + idx;
            out[R_OBJ + gidx] = score;
            g_keys[gidx] = ((u64)__float_as_uint(score) << 32) | (u64)(0xFFFFFFFFu - (u32)idx);

            float r  = (a == 0) ? 0.5f : ((a == 1) ? 1.f : 2.f);
            float sq = sqrtf(r);
            float ahh = sz * sq, aww = sz / sq;
            float x1 = cx - aww*0.5f, x2 = cx + aww*0.5f;
            float y1 = cy - ahh*0.5f, y2 = cy + ahh*0.5f;
            x1 = fminf(fmaxf(x1, 0.f), 1344.f); x2 = fminf(fmaxf(x2, 0.f), 1344.f);
            y1 = fminf(fmaxf(y1, 0.f),  800.f); y2 = fminf(fmaxf(y2, 0.f),  800.f);
            ((float4*)out)[gidx] = make_float4(x1, y1, x2, y2);   // anchors at region 0

            float dx = rv[a], dy = rv[3+a], dw = rv[6+a], dh = rv[9+a];
            ((float4*)(out + R_DELTA))[gidx] = make_float4(dx, dy, dw, dh);

            float aw2 = x2 - x1, ah2 = y2 - y1;
            float acx = y1 + aw2*0.5f;   // reference's swap quirk (faithful)
            float acy = x1 + ah2*0.5f;
            float px = acx + dx*aw2, py = acy + dy*ah2;
            float pw = aw2 * expf(dw), ph = ah2 * expf(dh);
            float bx1 = px - pw*0.5f, by1 = py - ph*0.5f;
            float bx2 = px + pw*0.5f, by2 = py + ph*0.5f;
            bx1 = fminf(fmaxf(bx1, 0.f), 1344.f); bx2 = fminf(fmaxf(bx2, 0.f), 1344.f);
            by1 = fminf(fmaxf(by1, 0.f),  800.f); by2 = fminf(fmaxf(by2, 0.f),  800.f);
            g_props[gidx] = make_float4(bx1, by1, bx2, by2);
        }
    }
}

// ---------------- radix-select: 8 x 8-bit passes, both levels in one sweep ----------------
__global__ void k_hist(int pass){
    __shared__ u32 h[512];
    for (int i = threadIdx.x; i < 512; i += blockDim.x) h[i] = 0u;
    __syncthreads();
    int shift = 56 - 8*pass;
    u64 p0 = g_prefix[0], p1 = g_prefix[1];
    for (int i = blockIdx.x*blockDim.x + threadIdx.x; i < NT; i += gridDim.x*blockDim.x){
        int lv = (i >= N0);
        u64 key = g_keys[i];
        bool ok = (pass == 0) || ((key >> (shift + 8)) == (lv ? p1 : p0));
        if (ok) atomicAdd(&h[(lv << 8) | (u32)((key >> shift) & 255)], 1u);
    }
    __syncthreads();
    for (int i = threadIdx.x; i < 512; i += blockDim.x){
        u32 v = h[i];
        if (v) atomicAdd(&g_hist[i>>8][i&255], v);
    }
}

__global__ void k_scan(){   // grid 2 (level), 256 threads — pick digit of the 2000th-largest key
    int lv = blockIdx.x, d = threadIdx.x;
    __shared__ u32 s[256];
    s[d] = g_hist[lv][d];
    __syncthreads();
    for (int off = 1; off < 256; off <<= 1){   // inclusive suffix sum
        u32 v = (d + off < 256) ? s[d + off] : 0u;
        __syncthreads();
        s[d] += v;
        __syncthreads();
    }
    u32 krem  = (u32)g_krem[lv];
    u32 suf   = s[d];
    u32 above = (d < 255) ? s[d+1] : 0u;
    if (above < krem && krem <= suf){
        g_prefix[lv] = (g_prefix[lv] << 8) | (u64)(u32)d;
        g_krem[lv]   = (int)(krem - above);
    }
    g_hist[lv][d] = 0u;
}

__global__ void k_compact(){
    u64 t0 = g_prefix[0], t1 = g_prefix[1];
    for (int i = blockIdx.x*blockDim.x + threadIdx.x; i < NT; i += gridDim.x*blockDim.x){
        int lv = (i >= N0);
        u64 key = g_keys[i];
        if (key >= (lv ? t1 : t0)){          // unique keys -> exactly 2000 pass per level
            int p = atomicAdd(&g_selcnt[lv], 1);
            if (p < 2048) g_selkeys[lv][p] = key;
        }
    }
}

// ---------------- bitonic sort 2048 (descending) + gather boxes/scores ----------------
__global__ void __launch_bounds__(1024) k_sortgather(){
    int lv = blockIdx.x, t = threadIdx.x;
    __shared__ u64 sk[2048];
    sk[t]        = g_selkeys[lv][t];
    sk[t + 1024] = g_selkeys[lv][t + 1024];
    __syncthreads();
    for (int k = 2; k <= 2048; k <<= 1){
        for (int j = k >> 1; j > 0; j >>= 1){
            int i1 = ((t & ~(j-1)) << 1) | (t & (j-1));
            int i2 = i1 + j;
            u64 a = sk[i1], b = sk[i2];
            bool up = ((i1 & k) == 0);
            if (up ? (a < b) : (a > b)){ sk[i1] = b; sk[i2] = a; }
            __syncthreads();
        }
    }
    int base = lv ? N0 : 0;
    for (int pos = t; pos < 2048; pos += 1024){
        u64 key = sk[pos];
        float sc = 0.f; float4 bx = make_float4(0.f, 0.f, 0.f, 0.f);
        if (pos < 2000){
            sc = __uint_as_float((u32)(key >> 32));
            u32 idx = 0xFFFFFFFFu - (u32)(key & 0xFFFFFFFFull);
            bx = g_props[base + idx];
        }
        g_selscore[lv][pos] = sc;
        g_selbox[lv][pos]   = bx;
    }
}

// ---------------- NMS bitmask build: row i, bits j>i with iou>0.7 ----------------
__global__ void __launch_bounds__(256) k_masks(){
    int lv = blockIdx.x / 250;
    int rb = blockIdx.x % 250;
    __shared__ float4 bs[2048];
    int tid = threadIdx.x;
    for (int s = tid; s < 2048; s += 256) bs[s] = g_selbox[lv][s];
    __syncthreads();
    int row = rb*8 + (tid >> 5);
    int jw  = tid & 31;
    float4 bi = bs[row];
    float ai = (bi.z - bi.x) * (bi.w - bi.y);
    u64 word = 0ull;
#pragma unroll 8
    for (int bb = 0; bb < 64; bb++){
        int j = jw*64 + bb;
        float4 bj = bs[j];
        float lx = fmaxf(bi.x, bj.x), ly = fmaxf(bi.y, bj.y);
        float rx = fminf(bi.z, bj.z), ry = fminf(bi.w, bj.w);
        float w = fmaxf(rx - lx, 0.f), h = fmaxf(ry - ly, 0.f);
        float inter = w * h;
        float aj = (bj.z - bj.x) * (bj.w - bj.y);
        float uni = fmaxf(ai + aj - inter, 1e-9f);
        float iou = inter / uni;
        if (j > row && iou > 0.7f) word |= (1ull << bb);
    }
    g_masks[lv][row*32 + jw] = word;
}

// ---------------- serial greedy NMS: one warp per level, 16-deep prefetch ----------------
__global__ void __launch_bounds__(32) k_reduce(){
    int lv = blockIdx.x, t = threadIdx.x;
    u64 keep = 0ull;
#pragma unroll 4
    for (int bb = 0; bb < 64; bb++){
        int i = t*64 + bb;
        if (i < 2000 && g_selscore[lv][i] > 0.f) keep |= (1ull << bb);
    }
    u64 pf[16];
#pragma unroll
    for (int d = 0; d < 16; d++) pf[d] = g_masks[lv][d*32 + t];
    for (int ib = 0; ib < 2000; ib += 16){
#pragma unroll
        for (int d = 0; d < 16; d++){
            int i = ib + d;
            u64 m = pf[d];
            int nx = i + 16;
            pf[d] = (nx < 2000) ? g_masks[lv][nx*32 + t] : 0ull;
            u64 kw = __shfl_sync(0xffffffffu, keep, i >> 6);
            if ((kw >> (i & 63)) & 1ull) keep &= ~m;
        }
    }
    g_keepw[lv][t] = keep;
}

// ---------------- stable compaction: kept entries in score order, first 1000 ----------------
__global__ void __launch_bounds__(256) k_output(float* __restrict__ out){
    int lv = blockIdx.x, tid = threadIdx.x;
    __shared__ u64 kw[32];
    __shared__ u32 P[32];
    if (tid < 32){
        u64 w = g_keepw[lv][tid];
        kw[tid] = w;
        u32 c = __popcll(w);
        u32 inc = c;
#pragma unroll
        for (int off = 1; off < 32; off <<= 1){
            u32 v = __shfl_up_sync(0xffffffffu, inc, off);
            if (tid >= off) inc += v;
        }
        P[tid] = inc - c;   // exclusive word prefix
    }
    __syncthreads();
    for (int i = tid; i < 2000; i += 256){
        int w = i >> 6, bb = i & 63;
        u64 word = kw[w];
        if ((word >> bb) & 1ull){
            u32 rank = P[w] + (u32)__popcll(word & ((1ull << bb) - 1ull));
            if (rank < 1000){
                out[R_FS + lv*1000 + rank] = g_selscore[lv][i];
                ((float4*)(out + R_FP))[lv*1000 + rank] = g_selbox[lv][i];
            }
        }
    }
}

extern "C" void kernel_launch(void* const* d_in, const int* in_sizes, int n_in,
                              void* d_out, int out_size){
    const float* fpn0 = (const float*)d_in[0];
    const float* fpn1 = (const float*)d_in[1];
    const float* cw0  = (const float*)d_in[2];
    const float* cb0  = (const float*)d_in[3];
    const float* cw1  = (const float*)d_in[4];
    const float* cb1  = (const float*)d_in[5];
    const float* detw = (const float*)d_in[6];
    const float* detb = (const float*)d_in[7];
    const float* regw = (const float*)d_in[8];
    const float* regb = (const float*)d_in[9];
    float* out = (float*)d_out;

    k_init<<<40, 256>>>(out);
    k_fold<<<18, 256>>>(cw0, cw1, detw, regw);
    k_foldb<<<1, 32>>>(cb0, cb1, detw, detb, regw, regb);
    k_conv<<<185, 128>>>(fpn0, fpn1, out);
    for (int p = 0; p < 8; p++){
        k_hist<<<264, 256>>>(p);
        k_scan<<<2, 256>>>();
    }
    k_compact<<<264, 256>>>();
    k_sortgather<<<2, 1024>>>();
    k_masks<<<500, 256>>>();
    k_reduce<<<2, 32>>>();
    k_output<<<2, 256>>>(out);
}

// round 11
// speedup vs baseline: 2.6806x; 2.6806x over previous
#include <cuda_runtime.h>
#include <math.h>

typedef unsigned long long u64;
typedef unsigned int u32;

// ---------------- problem constants ----------------
#define L0H 200
#define L0W 336
#define L1H 100
#define L1W 168
#define HW0 (L0H*L0W)      // 67200
#define HW1 (L1H*L1W)      // 16800
#define N0 (3*HW0)         // 201600
#define N1 (3*HW1)         // 50400
#define NT (N0+N1)         // 252000
// output regions (floats), tuple order:
// anchors (NT,4) | obj (1,NT) | f_scores (2000) | f_props (2000,4) | deltas (1,NT,4)
#define R_OBJ   (NT*4)          // 1008000
#define R_FS    (R_OBJ+NT)      // 1260000
#define R_FP    (R_FS+2000)     // 1262000
#define R_DELTA (R_FP+8000)     // 1270000

// ---------------- device scratch (static, no runtime alloc) ----------------
__device__ float  g_cw[2][2304][12];    // folded reg weights (fp32) [level][i*9+tap][o]
__device__ float  g_cwdh[2][2304][3];   // folded det weights hi (fp64 split)
__device__ float  g_cwdl[2][2304][3];   // folded det weights lo
__device__ float  g_cb[2][12];          // folded reg bias
__device__ float  g_cbdh[2][3];         // folded det bias hi
__device__ float  g_cbdl[2][3];         // folded det bias lo
__device__ float4 g_props[NT];          // decoded+clipped proposals
__device__ u64    g_keys[NT];           // (score_bits<<32)|(0xFFFFFFFF-idx): unique, stable tiebreak
__device__ u64    g_selkeys[2][2048];
__device__ float4 g_selbox[2][2048];
__device__ float  g_selscore[2][2048];
__device__ u64    g_masks[2][2000*32];  // NMS suppression bitmatrix (row i: bits j>i with iou>0.7)
__device__ u64    g_keepw[2][32];
__device__ u64    g_prefix[2];
__device__ int    g_krem[2];
__device__ int    g_selcnt[2];
__device__ u32    g_hist[2][256];

// ---------------- f32x2 helpers ----------------
__device__ __forceinline__ u64 pk2(float lo, float hi){
    u64 v; asm("mov.b64 %0,{%1,%2};" : "=l"(v) : "f"(lo), "f"(hi)); return v;
}
__device__ __forceinline__ void upk2(u64 v, float& lo, float& hi){
    asm("mov.b64 {%0,%1},%2;" : "=f"(lo), "=f"(hi) : "l"(v));
}
__device__ __forceinline__ u64 ff2(u64 a, u64 b, u64 c){
    u64 d; asm("fma.rn.f32x2 %0,%1,%2,%3;" : "=l"(d) : "l"(a), "l"(b), "l"(c)); return d;
}
__device__ __forceinline__ u64 add2(u64 a, u64 b){
    u64 d; asm("add.rn.f32x2 %0,%1,%2;" : "=l"(d) : "l"(a), "l"(b)); return d;
}
#define M1PACK 0xBF800000BF800000ull   // packed (-1.f, -1.f)

// ---------------- per-call init ----------------
__global__ void k_init(float* __restrict__ out){
    int t = blockIdx.x*blockDim.x + threadIdx.x;
    if (t < 2){ g_prefix[t] = 0ull; g_krem[t] = 2000; g_selcnt[t] = 0; }
    if (t < 512) g_hist[t>>8][t&255] = 0u;
    if (t < 96){ int lv = t/48; g_selkeys[lv][2000 + (t%48)] = 0ull; }
    if (t < 10000) out[R_FS + t] = 0.f;   // zero f_scores + f_props regions
}

// ---------------- fold weights: cw[lv][l][o] = sum_c head_w[o,c]*conv_w[c][l] ----------------
// det channels folded in fp64, stored as hi/lo fp32 split; reg channels fp32.
__global__ void __launch_bounds__(256) k_fold(const float* __restrict__ w30,
                                              const float* __restrict__ w31,
                                              const float* __restrict__ detw,
                                              const float* __restrict__ regw){
    __shared__ float  hwr[12*256];
    __shared__ double hwd[3*256];
    int tid = threadIdx.x;
    for (int s = tid; s < 12*256; s += 256){
        int o = s >> 8, c = s & 255;
        hwr[s] = regw[o*256 + c];
    }
    for (int s = tid; s < 3*256; s += 256){
        int o = s >> 8, c = s & 255;
        hwd[s] = (double)detw[o*256 + c];
    }
    __syncthreads();
    int lin = blockIdx.x*256 + tid;          // 0..4607
    int lv  = (lin >= 2304);
    int l   = lv ? (lin - 2304) : lin;       // 0..2303 = i*9 + tap
    const float* w3 = lv ? w31 : w30;
    float  fa[12];
    double da[3];
#pragma unroll
    for (int o = 0; o < 12; o++) fa[o] = 0.f;
#pragma unroll
    for (int a = 0; a < 3; a++) da[a] = 0.0;
    for (int c = 0; c < 256; c++){
        float x = w3[c*2304 + l];
        double xd = (double)x;
#pragma unroll
        for (int a = 0; a < 3; a++) da[a] += hwd[(a<<8) + c] * xd;
#pragma unroll
        for (int o = 0; o < 12; o++) fa[o] += hwr[(o<<8) + c] * x;
    }
#pragma unroll
    for (int o = 0; o < 12; o++) g_cw[lv][l][o] = fa[o];
#pragma unroll
    for (int a = 0; a < 3; a++){
        float hi = (float)da[a];
        g_cwdh[lv][l][a] = hi;
        g_cwdl[lv][l][a] = (float)(da[a] - (double)hi);
    }
}

__global__ void k_foldb(const float* __restrict__ cb0, const float* __restrict__ cb1,
                        const float* __restrict__ detw, const float* __restrict__ detb,
                        const float* __restrict__ regw, const float* __restrict__ regb){
    int t = threadIdx.x;
    if (t >= 32) return;
    int lv = t / 16, o = t % 16;
    const float* cb = lv ? cb1 : cb0;
    if (o < 3){
        double s = (double)detb[o];
        for (int c = 0; c < 256; c++) s += (double)detw[o*256 + c] * (double)cb[c];
        float hi = (float)s;
        g_cbdh[lv][o] = hi;
        g_cbdl[lv][o] = (float)(s - (double)hi);
    } else if (o < 15){
        int ro = o - 3;
        float s = regb[ro];
        for (int c = 0; c < 256; c++) s += regw[ro*256 + c] * cb[c];
        g_cb[lv][ro] = s;
    }
}

// ---------------- fused folded conv3x3 + sigmoid + anchors + decode ----------------
// tile 16H x 32W, 128 threads, 4 px/thread, all f32x2.
// det channels use compensated (hi/lo weight + error-free residual) accumulation
// -> logits accurate to ~1e-13, matching the fp64 path's fp32-rounded ranking.
__global__ void __launch_bounds__(128) k_conv(const float* __restrict__ x0,
                                              const float* __restrict__ x1,
                                              float* __restrict__ out){
    __shared__ float  xs[8][18][34];
    __shared__ u64    ws_reg[8*9*12];
    __shared__ u64    ws_dh[8*9*3];
    __shared__ u64    ws_dl[8*9*3];
    int b = blockIdx.x;
    int lv, H, W, lvbase, tx, ty; const float* xin;
    if (b < 143){ lv = 0; tx = b % 11; ty = b / 11; H = L0H; W = L0W; xin = x0; lvbase = 0;  }
    else { int c = b - 143; lv = 1; tx = c % 6; ty = c / 6; H = L1H; W = L1W; xin = x1; lvbase = N0; }
    int HW = H * W;
    int X0 = tx * 32, Y0 = ty * 16;
    int tid = threadIdx.x;
    int wcol = tid & 31, r0 = (tid >> 5) * 4;

    u64 racc[24];
    u64 ds[6], dc[6];
#pragma unroll
    for (int o = 0; o < 12; o++){
        float bb = g_cb[lv][o];
        u64 p = pk2(bb, bb);
        racc[2*o] = p; racc[2*o+1] = p;
    }
#pragma unroll
    for (int a = 0; a < 3; a++){
        float bh = g_cbdh[lv][a], bl = g_cbdl[lv][a];
        ds[2*a] = pk2(bh, bh); ds[2*a+1] = pk2(bh, bh);
        dc[2*a] = pk2(bl, bl); dc[2*a+1] = pk2(bl, bl);
    }

    for (int cc = 0; cc < 256; cc += 8){
        __syncthreads();
        for (int s = tid; s < 8*18*34; s += 128){
            int ic = s / 612; int rm = s - ic*612; int r = rm / 34; int c2 = rm - r*34;
            int gy = Y0 - 1 + r, gx = X0 - 1 + c2;
            float v = 0.f;
            if ((unsigned)gy < (unsigned)H && (unsigned)gx < (unsigned)W)
                v = xin[(cc+ic)*HW + gy*W + gx];
            xs[ic][r][c2] = v;
        }
        for (int s = tid; s < 864; s += 128){
            int ic = s / 108; int rm = s - ic*108; int tap = rm / 12; int o = rm - tap*12;
            float w = g_cw[lv][(cc+ic)*9 + tap][o];
            ws_reg[(ic*9 + tap)*12 + o] = pk2(w, w);
        }
        for (int s = tid; s < 216; s += 128){
            int ic = s / 27; int rm = s - ic*27; int tap = rm / 3; int a = rm - tap*3;
            float h = g_cwdh[lv][(cc+ic)*9 + tap][a];
            float l2 = g_cwdl[lv][(cc+ic)*9 + tap][a];
            ws_dh[(ic*9 + tap)*3 + a] = pk2(h, h);
            ws_dl[(ic*9 + tap)*3 + a] = pk2(l2, l2);
        }
        __syncthreads();
#pragma unroll 1
        for (int ic = 0; ic < 8; ic++){
            float xc[3][6];
#pragma unroll
            for (int kx = 0; kx < 3; kx++)
#pragma unroll
                for (int j = 0; j < 6; j++)
                    xc[kx][j] = xs[ic][r0 + j][wcol + kx];
#pragma unroll
            for (int ky = 0; ky < 3; ky++){
#pragma unroll
                for (int kx = 0; kx < 3; kx++){
                    u64 xv0 = pk2(xc[kx][ky],   xc[kx][ky+1]);
                    u64 xv1 = pk2(xc[kx][ky+2], xc[kx][ky+3]);
                    int tapi = ic*9 + ky*3 + kx;
                    const u64* wr = &ws_reg[tapi*12];
#pragma unroll
                    for (int o = 0; o < 12; o++){
                        u64 wv = wr[o];
                        racc[2*o]   = ff2(wv, xv0, racc[2*o]);
                        racc[2*o+1] = ff2(wv, xv1, racc[2*o+1]);
                    }
                    const u64* wdh = &ws_dh[tapi*3];
                    const u64* wdl = &ws_dl[tapi*3];
#pragma unroll
                    for (int a = 0; a < 3; a++){
                        u64 wh = wdh[a], wl = wdl[a];
                        {   // pixel pair 0
                            u64 s  = ds[2*a];
                            u64 s2 = ff2(wh, xv0, s);
                            u64 t  = ff2(s2, M1PACK, s);      // s - s2 (exact)
                            u64 e  = ff2(wh, xv0, t);         // FMA residual
                            u64 c2 = add2(dc[2*a], e);
                            dc[2*a] = ff2(wl, xv0, c2);       // + lo-weight term
                            ds[2*a] = s2;
                        }
                        {   // pixel pair 1
                            u64 s  = ds[2*a+1];
                            u64 s2 = ff2(wh, xv1, s);
                            u64 t  = ff2(s2, M1PACK, s);
                            u64 e  = ff2(wh, xv1, t);
                            u64 c2 = add2(dc[2*a+1], e);
                            dc[2*a+1] = ff2(wl, xv1, c2);
                            ds[2*a+1] = s2;
                        }
                    }
                }
            }
        }
    }

    // epilogue: sigmoid, anchors (clipped), deltas, decode (with ref's x/y-center swap), clip
    float scale = lv ? 8.f : 4.f;
    float sz    = lv ? 64.f : 32.f;
#pragma unroll
    for (int p = 0; p < 4; p++){
        int gy = Y0 + r0 + p, gx = X0 + wcol;
        if (gy >= H || gx >= W) continue;
        float rv[12];
#pragma unroll
        for (int o = 0; o < 12; o++){
            float lo, hi; upk2(racc[2*o + (p>>1)], lo, hi);
            rv[o] = (p & 1) ? hi : lo;
        }
        float dlog[3];
#pragma unroll
        for (int a = 0; a < 3; a++){
            float slo, shi, clo, chi;
            upk2(ds[2*a + (p>>1)], slo, shi);
            upk2(dc[2*a + (p>>1)], clo, chi);
            dlog[a] = (p & 1) ? (shi + chi) : (slo + clo);
        }
        int pix = gy*W + gx;
        float cx = (gx + 0.5f) * scale, cy = (gy + 0.5f) * scale;
#pragma unroll
        for (int a = 0; a < 3; a++){
            float score = 1.f / (1.f + expf(-dlog[a]));
            int idx  = a*HW + pix;
            int gidx = lvbase + idx;
            out[R_OBJ + gidx] = score;
            g_keys[gidx] = ((u64)__float_as_uint(score) << 32) | (u64)(0xFFFFFFFFu - (u32)idx);

            float r  = (a == 0) ? 0.5f : ((a == 1) ? 1.f : 2.f);
            float sq = sqrtf(r);
            float ahh = sz * sq, aww = sz / sq;
            float x1 = cx - aww*0.5f, x2 = cx + aww*0.5f;
            float y1 = cy - ahh*0.5f, y2 = cy + ahh*0.5f;
            x1 = fminf(fmaxf(x1, 0.f), 1344.f); x2 = fminf(fmaxf(x2, 0.f), 1344.f);
            y1 = fminf(fmaxf(y1, 0.f),  800.f); y2 = fminf(fmaxf(y2, 0.f),  800.f);
            ((float4*)out)[gidx] = make_float4(x1, y1, x2, y2);   // anchors at region 0

            float dx = rv[a], dy = rv[3+a], dw = rv[6+a], dh = rv[9+a];
            ((float4*)(out + R_DELTA))[gidx] = make_float4(dx, dy, dw, dh);

            float aw2 = x2 - x1, ah2 = y2 - y1;
            float acx = y1 + aw2*0.5f;   // reference's swap quirk (faithful)
            float acy = x1 + ah2*0.5f;
            float px = acx + dx*aw2, py = acy + dy*ah2;
            float pw = aw2 * expf(dw), ph = ah2 * expf(dh);
            float bx1 = px - pw*0.5f, by1 = py - ph*0.5f;
            float bx2 = px + pw*0.5f, by2 = py + ph*0.5f;
            bx1 = fminf(fmaxf(bx1, 0.f), 1344.f); bx2 = fminf(fmaxf(bx2, 0.f), 1344.f);
            by1 = fminf(fmaxf(by1, 0.f),  800.f); by2 = fminf(fmaxf(by2, 0.f),  800.f);
            g_props[gidx] = make_float4(bx1, by1, bx2, by2);
        }
    }
}

// ---------------- radix-select: 8 x 8-bit passes, both levels in one sweep ----------------
__global__ void k_hist(int pass){
    __shared__ u32 h[512];
    for (int i = threadIdx.x; i < 512; i += blockDim.x) h[i] = 0u;
    __syncthreads();
    int shift = 56 - 8*pass;
    u64 p0 = g_prefix[0], p1 = g_prefix[1];
    for (int i = blockIdx.x*blockDim.x + threadIdx.x; i < NT; i += gridDim.x*blockDim.x){
        int lv = (i >= N0);
        u64 key = g_keys[i];
        bool ok = (pass == 0) || ((key >> (shift + 8)) == (lv ? p1 : p0));
        if (ok) atomicAdd(&h[(lv << 8) | (u32)((key >> shift) & 255)], 1u);
    }
    __syncthreads();
    for (int i = threadIdx.x; i < 512; i += blockDim.x){
        u32 v = h[i];
        if (v) atomicAdd(&g_hist[i>>8][i&255], v);
    }
}

__global__ void k_scan(){   // grid 2 (level), 256 threads — pick digit of the 2000th-largest key
    int lv = blockIdx.x, d = threadIdx.x;
    __shared__ u32 s[256];
    s[d] = g_hist[lv][d];
    __syncthreads();
    for (int off = 1; off < 256; off <<= 1){   // inclusive suffix sum
        u32 v = (d + off < 256) ? s[d + off] : 0u;
        __syncthreads();
        s[d] += v;
        __syncthreads();
    }
    u32 krem  = (u32)g_krem[lv];
    u32 suf   = s[d];
    u32 above = (d < 255) ? s[d+1] : 0u;
    if (above < krem && krem <= suf){
        g_prefix[lv] = (g_prefix[lv] << 8) | (u64)(u32)d;
        g_krem[lv]   = (int)(krem - above);
    }
    g_hist[lv][d] = 0u;
}

__global__ void k_compact(){
    u64 t0 = g_prefix[0], t1 = g_prefix[1];
    for (int i = blockIdx.x*blockDim.x + threadIdx.x; i < NT; i += gridDim.x*blockDim.x){
        int lv = (i >= N0);
        u64 key = g_keys[i];
        if (key >= (lv ? t1 : t0)){          // unique keys -> exactly 2000 pass per level
            int p = atomicAdd(&g_selcnt[lv], 1);
            if (p < 2048) g_selkeys[lv][p] = key;
        }
    }
}

// ---------------- bitonic sort 2048 (descending) + gather boxes/scores ----------------
__global__ void __launch_bounds__(1024) k_sortgather(){
    int lv = blockIdx.x, t = threadIdx.x;
    __shared__ u64 sk[2048];
    sk[t]        = g_selkeys[lv][t];
    sk[t + 1024] = g_selkeys[lv][t + 1024];
    __syncthreads();
    for (int k = 2; k <= 2048; k <<= 1){
        for (int j = k >> 1; j > 0; j >>= 1){
            int i1 = ((t & ~(j-1)) << 1) | (t & (j-1));
            int i2 = i1 + j;
            u64 a = sk[i1], b = sk[i2];
            bool up = ((i1 & k) == 0);
            if (up ? (a < b) : (a > b)){ sk[i1] = b; sk[i2] = a; }
            __syncthreads();
        }
    }
    int base = lv ? N0 : 0;
    for (int pos = t; pos < 2048; pos += 1024){
        u64 key = sk[pos];
        float sc = 0.f; float4 bx = make_float4(0.f, 0.f, 0.f, 0.f);
        if (pos < 2000){
            sc = __uint_as_float((u32)(key >> 32));
            u32 idx = 0xFFFFFFFFu - (u32)(key & 0xFFFFFFFFull);
            bx = g_props[base + idx];
        }
        g_selscore[lv][pos] = sc;
        g_selbox[lv][pos]   = bx;
    }
}

// ---------------- NMS bitmask build (ballot, conflict-free, triangular skip) ----------------
__global__ void __launch_bounds__(256) k_masks(){
    int lv = blockIdx.x / 250;
    int rb = blockIdx.x % 250;
    __shared__ float4 bs[2048];
    int tid = threadIdx.x;
    for (int s = tid; s < 2048; s += 256) bs[s] = g_selbox[lv][s];
    __syncthreads();
    int row  = rb*8 + (tid >> 5);
    int lane = tid & 31;
    float4 bi = bs[row];
    float ai = (bi.z - bi.x) * (bi.w - bi.y);
    u64 word = 0ull;
    int rs = (row >= 31) ? ((row - 31) >> 5) : 0;   // rounds with any j > row
    for (int r = rs; r < 64; r++){
        int j = r*32 + lane;                         // lane-contiguous: no bank conflicts
        float4 bj = bs[j];
        float lx = fmaxf(bi.x, bj.x), ly = fmaxf(bi.y, bj.y);
        float rx = fminf(bi.z, bj.z), ry = fminf(bi.w, bj.w);
        float w = fmaxf(rx - lx, 0.f), h = fmaxf(ry - ly, 0.f);
        float inter = w * h;
        float aj = (bj.z - bj.x) * (bj.w - bj.y);
        float uni = fmaxf(ai + aj - inter, 1e-9f);
        bool pred = (j > row) && (inter > 0.7f * uni);
        u32 bal = __ballot_sync(0xffffffffu, pred);
        if (lane == (r >> 1))
            word |= (r & 1) ? ((u64)bal << 32) : (u64)bal;
    }
    g_masks[lv][row*32 + lane] = word;
}

// ---------------- serial greedy NMS: one warp per level, 16-deep prefetch ----------------
__global__ void __launch_bounds__(32) k_reduce(){
    int lv = blockIdx.x, t = threadIdx.x;
    u64 keep = 0ull;
#pragma unroll 4
    for (int bb = 0; bb < 64; bb++){
        int i = t*64 + bb;
        if (i < 2000 && g_selscore[lv][i] > 0.f) keep |= (1ull << bb);
    }
    u64 pf[16];
#pragma unroll
    for (int d = 0; d < 16; d++) pf[d] = g_masks[lv][d*32 + t];
    for (int ib = 0; ib < 2000; ib += 16){
#pragma unroll
        for (int d = 0; d < 16; d++){
            int i = ib + d;
            u64 m = pf[d];
            int nx = i + 16;
            pf[d] = (nx < 2000) ? g_masks[lv][nx*32 + t] : 0ull;
            u64 kw = __shfl_sync(0xffffffffu, keep, i >> 6);
            if ((kw >> (i & 63)) & 1ull) keep &= ~m;
        }
    }
    g_keepw[lv][t] = keep;
}

// ---------------- stable compaction: kept entries in score order, first 1000 ----------------
__global__ void __launch_bounds__(256) k_output(float* __restrict__ out){
    int lv = blockIdx.x, tid = threadIdx.x;
    __shared__ u64 kw[32];
    __shared__ u32 P[32];
    if (tid < 32){
        u64 w = g_keepw[lv][tid];
        kw[tid] = w;
        u32 c = __popcll(w);
        u32 inc = c;
#pragma unroll
        for (int off = 1; off < 32; off <<= 1){
            u32 v = __shfl_up_sync(0xffffffffu, inc, off);
            if (tid >= off) inc += v;
        }
        P[tid] = inc - c;   // exclusive word prefix
    }
    __syncthreads();
    for (int i = tid; i < 2000; i += 256){
        int w = i >> 6, bb = i & 63;
        u64 word = kw[w];
        if ((word >> bb) & 1ull){
            u32 rank = P[w] + (u32)__popcll(word & ((1ull << bb) - 1ull));
            if (rank < 1000){
                out[R_FS + lv*1000 + rank] = g_selscore[lv][i];
                ((float4*)(out + R_FP))[lv*1000 + rank] = g_selbox[lv][i];
            }
        }
    }
}

extern "C" void kernel_launch(void* const* d_in, const int* in_sizes, int n_in,
                              void* d_out, int out_size){
    const float* fpn0 = (const float*)d_in[0];
    const float* fpn1 = (const float*)d_in[1];
    const float* cw0  = (const float*)d_in[2];
    const float* cb0  = (const float*)d_in[3];
    const float* cw1  = (const float*)d_in[4];
    const float* cb1  = (const float*)d_in[5];
    const float* detw = (const float*)d_in[6];
    const float* detb = (const float*)d_in[7];
    const float* regw = (const float*)d_in[8];
    const float* regb = (const float*)d_in[9];
    float* out = (float*)d_out;

    k_init<<<40, 256>>>(out);
    k_fold<<<18, 256>>>(cw0, cw1, detw, regw);
    k_foldb<<<1, 32>>>(cb0, cb1, detw, detb, regw, regb);
    k_conv<<<185, 128>>>(fpn0, fpn1, out);
    for (int p = 0; p < 8; p++){
        k_hist<<<148, 256>>>(p);
        k_scan<<<2, 256>>>();
    }
    k_compact<<<148, 256>>>();
    k_sortgather<<<2, 1024>>>();
    k_masks<<<500, 256>>>();
    k_reduce<<<2, 32>>>();
    k_output<<<2, 256>>>(out);
}

// round 14
// speedup vs baseline: 3.3655x; 1.2555x over previous
#include <cuda_runtime.h>
#include <math.h>

typedef unsigned long long u64;
typedef unsigned int u32;

// ---------------- problem constants ----------------
#define L0H 200
#define L0W 336
#define L1H 100
#define L1W 168
#define HW0 (L0H*L0W)      // 67200
#define HW1 (L1H*L1W)      // 16800
#define N0 (3*HW0)         // 201600
#define N1 (3*HW1)         // 50400
#define NT (N0+N1)         // 252000
// output regions (floats), tuple order:
// anchors (NT,4) | obj (1,NT) | f_scores (2000) | f_props (2000,4) | deltas (1,NT,4)
#define R_OBJ   (NT*4)          // 1008000
#define R_FS    (R_OBJ+NT)      // 1260000
#define R_FP    (R_FS+2000)     // 1262000
#define R_DELTA (R_FP+8000)     // 1270000

#define CAND_CAP 131072

// ---------------- device scratch (static, no runtime alloc) ----------------
__device__ float  g_cw[2][2304][12];    // folded reg weights (fp32) [level][i*9+tap][o]
__device__ float  g_cwdh[2][2304][3];   // folded det weights hi (fp64 split)
__device__ float  g_cwdl[2][2304][3];   // folded det weights lo
__device__ float  g_cb[2][12];          // folded reg bias
__device__ float  g_cbdh[2][3];         // folded det bias hi
__device__ float  g_cbdl[2][3];         // folded det bias lo
__device__ float4 g_props[NT];          // decoded+clipped proposals
__device__ u64    g_keys[NT];           // (score_bits<<32)|(0xFFFFFFFF-idx): unique, stable tiebreak
__device__ u64    g_cand[2][CAND_CAP];  // radix candidate lists (keys >= prefix16<<48)
__device__ int    g_candcnt[2];
__device__ u64    g_selkeys[2][2048];
__device__ float4 g_selbox[2][2048];
__device__ float  g_selscore[2][2048];
__device__ u64    g_masks[2][2000*32];  // NMS suppression bitmatrix (row i: bits j>i with iou>0.7)
__device__ u64    g_keepw[2][32];
__device__ u64    g_prefix[2];
__device__ int    g_krem[2];
__device__ int    g_selcnt[2];
__device__ u32    g_hist[2][256];

// ---------------- f32x2 helpers ----------------
__device__ __forceinline__ u64 pk2(float lo, float hi){
    u64 v; asm("mov.b64 %0,{%1,%2};" : "=l"(v) : "f"(lo), "f"(hi)); return v;
}
__device__ __forceinline__ void upk2(u64 v, float& lo, float& hi){
    asm("mov.b64 {%0,%1},%2;" : "=f"(lo), "=f"(hi) : "l"(v));
}
__device__ __forceinline__ u64 ff2(u64 a, u64 b, u64 c){
    u64 d; asm("fma.rn.f32x2 %0,%1,%2,%3;" : "=l"(d) : "l"(a), "l"(b), "l"(c)); return d;
}
__device__ __forceinline__ u64 add2(u64 a, u64 b){
    u64 d; asm("add.rn.f32x2 %0,%1,%2;" : "=l"(d) : "l"(a), "l"(b)); return d;
}
#define M1PACK 0xBF800000BF800000ull   // packed (-1.f, -1.f)

// ---------------- per-call init ----------------
__global__ void k_init(float* __restrict__ out){
    int t = blockIdx.x*blockDim.x + threadIdx.x;
    if (t < 2){ g_prefix[t] = 0ull; g_krem[t] = 2000; g_selcnt[t] = 0; g_candcnt[t] = 0; }
    if (t < 512) g_hist[t>>8][t&255] = 0u;
    if (t < 96){ int lv = t/48; g_selkeys[lv][2000 + (t%48)] = 0ull; }
    if (t < 10000) out[R_FS + t] = 0.f;   // zero f_scores + f_props regions
}

// ---------------- fold weights: cw[lv][l][o] = sum_c head_w[o,c]*conv_w[c][l] ----------------
// det channels folded in fp64, stored as hi/lo fp32 split; reg channels fp32.
__global__ void __launch_bounds__(256) k_fold(const float* __restrict__ w30,
                                              const float* __restrict__ w31,
                                              const float* __restrict__ detw,
                                              const float* __restrict__ regw){
    __shared__ float  hwr[12*256];
    __shared__ double hwd[3*256];
    int tid = threadIdx.x;
    for (int s = tid; s < 12*256; s += 256){
        int o = s >> 8, c = s & 255;
        hwr[s] = regw[o*256 + c];
    }
    for (int s = tid; s < 3*256; s += 256){
        int o = s >> 8, c = s & 255;
        hwd[s] = (double)detw[o*256 + c];
    }
    __syncthreads();
    int lin = blockIdx.x*256 + tid;          // 0..4607
    int lv  = (lin >= 2304);
    int l   = lv ? (lin - 2304) : lin;       // 0..2303 = i*9 + tap
    const float* w3 = lv ? w31 : w30;
    float  fa[12];
    double da[3];
#pragma unroll
    for (int o = 0; o < 12; o++) fa[o] = 0.f;
#pragma unroll
    for (int a = 0; a < 3; a++) da[a] = 0.0;
    for (int c = 0; c < 256; c++){
        float x = w3[c*2304 + l];
        double xd = (double)x;
#pragma unroll
        for (int a = 0; a < 3; a++) da[a] += hwd[(a<<8) + c] * xd;
#pragma unroll
        for (int o = 0; o < 12; o++) fa[o] += hwr[(o<<8) + c] * x;
    }
#pragma unroll
    for (int o = 0; o < 12; o++) g_cw[lv][l][o] = fa[o];
#pragma unroll
    for (int a = 0; a < 3; a++){
        float hi = (float)da[a];
        g_cwdh[lv][l][a] = hi;
        g_cwdl[lv][l][a] = (float)(da[a] - (double)hi);
    }
}

__global__ void k_foldb(const float* __restrict__ cb0, const float* __restrict__ cb1,
                        const float* __restrict__ detw, const float* __restrict__ detb,
                        const float* __restrict__ regw, const float* __restrict__ regb){
    int t = threadIdx.x;
    if (t >= 32) return;
    int lv = t / 16, o = t % 16;
    const float* cb = lv ? cb1 : cb0;
    if (o < 3){
        double s = (double)detb[o];
        for (int c = 0; c < 256; c++) s += (double)detw[o*256 + c] * (double)cb[c];
        float hi = (float)s;
        g_cbdh[lv][o] = hi;
        g_cbdl[lv][o] = (float)(s - (double)hi);
    } else if (o < 15){
        int ro = o - 3;
        float s = regb[ro];
        for (int c = 0; c < 256; c++) s += regw[ro*256 + c] * cb[c];
        g_cb[lv][ro] = s;
    }
}

// ---------------- fused folded conv3x3 + sigmoid + anchors + decode ----------------
// tile 8H x 32W, 128 threads, 2 px/thread (one f32x2 pair along H).
// 353 blocks -> ~2.4 warps/scheduler (vs 1.25 before): latency-hiding fix.
// det channels: compensated (hi/lo weight + error-free residual) accumulation.
__global__ void __launch_bounds__(128) k_conv(const float* __restrict__ x0,
                                              const float* __restrict__ x1,
                                              float* __restrict__ out){
    __shared__ float  xs[8][10][34];
    __shared__ u64    ws_reg[8*9*12];
    __shared__ u64    ws_dh[8*9*3];
    __shared__ u64    ws_dl[8*9*3];
    int b = blockIdx.x;
    int lv, H, W, lvbase, tx, ty; const float* xin;
    if (b < 275){ lv = 0; tx = b % 11; ty = b / 11; H = L0H; W = L0W; xin = x0; lvbase = 0;  }
    else { int c = b - 275; lv = 1; tx = c % 6; ty = c / 6; H = L1H; W = L1W; xin = x1; lvbase = N0; }
    int HW = H * W;
    int X0 = tx * 32, Y0 = ty * 8;
    int tid = threadIdx.x;
    int wcol = tid & 31, r0 = (tid >> 5) * 2;

    u64 racc[12];
    u64 ds[3], dc[3];
#pragma unroll
    for (int o = 0; o < 12; o++){
        float bb = g_cb[lv][o];
        racc[o] = pk2(bb, bb);
    }
#pragma unroll
    for (int a = 0; a < 3; a++){
        float bh = g_cbdh[lv][a], bl = g_cbdl[lv][a];
        ds[a] = pk2(bh, bh);
        dc[a] = pk2(bl, bl);
    }

    for (int cc = 0; cc < 256; cc += 8){
        __syncthreads();
        for (int s = tid; s < 8*10*34; s += 128){
            int ic = s / 340; int rm = s - ic*340; int r = rm / 34; int c2 = rm - r*34;
            int gy = Y0 - 1 + r, gx = X0 - 1 + c2;
            float v = 0.f;
            if ((unsigned)gy < (unsigned)H && (unsigned)gx < (unsigned)W)
                v = xin[(cc+ic)*HW + gy*W + gx];
            xs[ic][r][c2] = v;
        }
        for (int s = tid; s < 864; s += 128){
            int ic = s / 108; int rm = s - ic*108; int tap = rm / 12; int o = rm - tap*12;
            float w = g_cw[lv][(cc+ic)*9 + tap][o];
            ws_reg[(ic*9 + tap)*12 + o] = pk2(w, w);
        }
        for (int s = tid; s < 216; s += 128){
            int ic = s / 27; int rm = s - ic*27; int tap = rm / 3; int a = rm - tap*3;
            float h = g_cwdh[lv][(cc+ic)*9 + tap][a];
            float l2 = g_cwdl[lv][(cc+ic)*9 + tap][a];
            ws_dh[(ic*9 + tap)*3 + a] = pk2(h, h);
            ws_dl[(ic*9 + tap)*3 + a] = pk2(l2, l2);
        }
        __syncthreads();
#pragma unroll 1
        for (int ic = 0; ic < 8; ic++){
            float xc[3][4];
#pragma unroll
            for (int kx = 0; kx < 3; kx++)
#pragma unroll
                for (int m = 0; m < 4; m++)
                    xc[kx][m] = xs[ic][r0 + m][wcol + kx];
#pragma unroll
            for (int ky = 0; ky < 3; ky++){
#pragma unroll
                for (int kx = 0; kx < 3; kx++){
                    u64 xv = pk2(xc[kx][ky], xc[kx][ky+1]);
                    int tapi = ic*9 + ky*3 + kx;
                    const u64* wr = &ws_reg[tapi*12];
#pragma unroll
                    for (int o = 0; o < 12; o++)
                        racc[o] = ff2(wr[o], xv, racc[o]);
                    const u64* wdh = &ws_dh[tapi*3];
                    const u64* wdl = &ws_dl[tapi*3];
#pragma unroll
                    for (int a = 0; a < 3; a++){
                        u64 wh = wdh[a], wl = wdl[a];
                        u64 s  = ds[a];
                        u64 s2 = ff2(wh, xv, s);
                        u64 t  = ff2(s2, M1PACK, s);      // s - s2 (exact)
                        u64 e  = ff2(wh, xv, t);          // FMA residual
                        u64 c2 = add2(dc[a], e);
                        dc[a]  = ff2(wl, xv, c2);         // + lo-weight term
                        ds[a]  = s2;
                    }
                }
            }
        }
    }

    // epilogue: sigmoid, anchors (clipped), deltas, decode (with ref's x/y-center swap), clip
    float scale = lv ? 8.f : 4.f;
    float sz    = lv ? 64.f : 32.f;
#pragma unroll
    for (int p = 0; p < 2; p++){
        int gy = Y0 + r0 + p, gx = X0 + wcol;
        if (gy >= H || gx >= W) continue;
        float rv[12];
#pragma unroll
        for (int o = 0; o < 12; o++){
            float lo, hi; upk2(racc[o], lo, hi);
            rv[o] = p ? hi : lo;
        }
        float dlog[3];
#pragma unroll
        for (int a = 0; a < 3; a++){
            float slo, shi, clo, chi;
            upk2(ds[a], slo, shi);
            upk2(dc[a], clo, chi);
            dlog[a] = p ? (shi + chi) : (slo + clo);
        }
        int pix = gy*W + gx;
        float cx = (gx + 0.5f) * scale, cy = (gy + 0.5f) * scale;
#pragma unroll
        for (int a = 0; a < 3; a++){
            float score = 1.f / (1.f + expf(-dlog[a]));
            int idx  = a*HW + pix;
            int gidx = lvbase + idx;
            out[R_OBJ + gidx] = score;
            g_keys[gidx] = ((u64)__float_as_uint(score) << 32) | (u64)(0xFFFFFFFFu - (u32)idx);

            float r  = (a == 0) ? 0.5f : ((a == 1) ? 1.f : 2.f);
            float sq = sqrtf(r);
            float ahh = sz * sq, aww = sz / sq;
            float x1 = cx - aww*0.5f, x2 = cx + aww*0.5f;
            float y1 = cy - ahh*0.5f, y2 = cy + ahh*0.5f;
            x1 = fminf(fmaxf(x1, 0.f), 1344.f); x2 = fminf(fmaxf(x2, 0.f), 1344.f);
            y1 = fminf(fmaxf(y1, 0.f),  800.f); y2 = fminf(fmaxf(y2, 0.f),  800.f);
            ((float4*)out)[gidx] = make_float4(x1, y1, x2, y2);   // anchors at region 0

            float dx = rv[a], dy = rv[3+a], dw = rv[6+a], dh = rv[9+a];
            ((float4*)(out + R_DELTA))[gidx] = make_float4(dx, dy, dw, dh);

            float aw2 = x2 - x1, ah2 = y2 - y1;
            float acx = y1 + aw2*0.5f;   // reference's swap quirk (faithful)
            float acy = x1 + ah2*0.5f;
            float px = acx + dx*aw2, py = acy + dy*ah2;
            float pw = aw2 * expf(dw), ph = ah2 * expf(dh);
            float bx1 = px - pw*0.5f, by1 = py - ph*0.5f;
            float bx2 = px + pw*0.5f, by2 = py + ph*0.5f;
            bx1 = fminf(fmaxf(bx1, 0.f), 1344.f); bx2 = fminf(fmaxf(bx2, 0.f), 1344.f);
            by1 = fminf(fmaxf(by1, 0.f),  800.f); by2 = fminf(fmaxf(by2, 0.f),  800.f);
            g_props[gidx] = make_float4(bx1, by1, bx2, by2);
        }
    }
}

// ---------------- radix-select ----------------
// pass 0/1: full-sweep 8-bit histograms (bytes 63-56, 55-48)
__global__ void k_hist(int pass){
    __shared__ u32 h[512];
    for (int i = threadIdx.x; i < 512; i += blockDim.x) h[i] = 0u;
    __syncthreads();
    int shift = 56 - 8*pass;
    u64 p0 = g_prefix[0], p1 = g_prefix[1];
    for (int i = blockIdx.x*blockDim.x + threadIdx.x; i < NT; i += gridDim.x*blockDim.x){
        int lv = (i >= N0);
        u64 key = g_keys[i];
        bool ok = (pass == 0) || ((key >> (shift + 8)) == (lv ? p1 : p0));
        if (ok) atomicAdd(&h[(lv << 8) | (u32)((key >> shift) & 255)], 1u);
    }
    __syncthreads();
    for (int i = threadIdx.x; i < 512; i += blockDim.x){
        u32 v = h[i];
        if (v) atomicAdd(&g_hist[i>>8][i&255], v);
    }
}

__global__ void k_scan(){   // grid 2 (level): pick digit of the 2000th-largest key, zero hist
    int lv = blockIdx.x, d = threadIdx.x;
    __shared__ u32 s[256];
    s[d] = g_hist[lv][d];
    __syncthreads();
    for (int off = 1; off < 256; off <<= 1){   // inclusive suffix sum
        u32 v = (d + off < 256) ? s[d + off] : 0u;
        __syncthreads();
        s[d] += v;
        __syncthreads();
    }
    u32 krem  = (u32)g_krem[lv];
    u32 suf   = s[d];
    u32 above = (d < 255) ? s[d+1] : 0u;
    if (above < krem && krem <= suf){
        g_prefix[lv] = (g_prefix[lv] << 8) | (u64)(u32)d;
        g_krem[lv]   = (int)(krem - above);
    }
    g_hist[lv][d] = 0u;
}

// full sweep: collect all keys >= (prefix16 << 48) into candidate list; hist byte 2.
// The list is a superset of the final selection; subsequent passes touch only it.
__global__ void k_build(){
    __shared__ u32 h[512];
    for (int i = threadIdx.x; i < 512; i += blockDim.x) h[i] = 0u;
    __syncthreads();
    u64 p0 = g_prefix[0], p1 = g_prefix[1];
    for (int i = blockIdx.x*blockDim.x + threadIdx.x; i < NT; i += gridDim.x*blockDim.x){
        int lv = (i >= N0);
        u64 key = g_keys[i];
        u64 top2 = key >> 48;
        u64 pref = lv ? p1 : p0;
        if (top2 >= pref){
            int p = atomicAdd(&g_candcnt[lv], 1);
            if (p < CAND_CAP) g_cand[lv][p] = key;
            if (top2 == pref)
                atomicAdd(&h[(lv << 8) | (u32)((key >> 40) & 255)], 1u);
        }
    }
    __syncthreads();
    for (int i = threadIdx.x; i < 512; i += blockDim.x){
        u32 v = h[i];
        if (v) atomicAdd(&g_hist[i>>8][i&255], v);
    }
}

// passes 3..7: scan previous byte's hist, then histogram current byte over candidates.
__global__ void __launch_bounds__(256) k_step(int pass){
    int lv = blockIdx.x, d = threadIdx.x;
    __shared__ u32 s[256];
    __shared__ u32 h[256];
    __shared__ u64 spref;
    s[d] = g_hist[lv][d];
    h[d] = 0u;
    __syncthreads();
    for (int off = 1; off < 256; off <<= 1){
        u32 v = (d + off < 256) ? s[d + off] : 0u;
        __syncthreads();
        s[d] += v;
        __syncthreads();
    }
    u32 krem  = (u32)g_krem[lv];
    u32 suf   = s[d];
    u32 above = (d < 255) ? s[d+1] : 0u;
    if (above < krem && krem <= suf){
        u64 np = (g_prefix[lv] << 8) | (u64)(u32)d;
        g_prefix[lv] = np;
        g_krem[lv]   = (int)(krem - above);
        spref = np;
    }
    __syncthreads();
    u64 pref = spref;
    int shift = 56 - 8*pass;
    int n = g_candcnt[lv]; if (n > CAND_CAP) n = CAND_CAP;
    for (int i = d; i < n; i += 256){
        u64 key = g_cand[lv][i];
        if ((key >> (shift + 8)) == pref)
            atomicAdd(&h[(u32)((key >> shift) & 255)], 1u);
    }
    __syncthreads();
    g_hist[lv][d] = h[d];
}

// final: scan byte 7 -> full 64-bit threshold; compact candidates >= threshold.
__global__ void __launch_bounds__(256) k_final(){
    int lv = blockIdx.x, d = threadIdx.x;
    __shared__ u32 s[256];
    __shared__ u64 sthr;
    __shared__ int scnt;
    s[d] = g_hist[lv][d];
    if (d == 0) scnt = 0;
    __syncthreads();
    for (int off = 1; off < 256; off <<= 1){
        u32 v = (d + off < 256) ? s[d + off] : 0u;
        __syncthreads();
        s[d] += v;
        __syncthreads();
    }
    u32 krem  = (u32)g_krem[lv];
    u32 suf   = s[d];
    u32 above = (d < 255) ? s[d+1] : 0u;
    if (above < krem && krem <= suf){
        u64 thr = (g_prefix[lv] << 8) | (u64)(u32)d;
        sthr = thr;
    }
    __syncthreads();
    u64 thr = sthr;
    int n = g_candcnt[lv]; if (n > CAND_CAP) n = CAND_CAP;
    for (int i = d; i < n; i += 256){
        u64 key = g_cand[lv][i];
        if (key >= thr){                 // unique keys -> exactly 2000 pass
            int p = atomicAdd(&scnt, 1);
            if (p < 2048) g_selkeys[lv][p] = key;
        }
    }
}

// ---------------- bitonic sort 2048 (descending) + gather boxes/scores ----------------
__global__ void __launch_bounds__(1024) k_sortgather(){
    int lv = blockIdx.x, t = threadIdx.x;
    __shared__ u64 sk[2048];
    sk[t]        = g_selkeys[lv][t];
    sk[t + 1024] = g_selkeys[lv][t + 1024];
    __syncthreads();
    for (int k = 2; k <= 2048; k <<= 1){
        for (int j = k >> 1; j > 0; j >>= 1){
            int i1 = ((t & ~(j-1)) << 1) | (t & (j-1));
            int i2 = i1 + j;
            u64 a = sk[i1], b = sk[i2];
            bool up = ((i1 & k) == 0);
            if (up ? (a < b) : (a > b)){ sk[i1] = b; sk[i2] = a; }
            __syncthreads();
        }
    }
    int base = lv ? N0 : 0;
    for (int pos = t; pos < 2048; pos += 1024){
        u64 key = sk[pos];
        float sc = 0.f; float4 bx = make_float4(0.f, 0.f, 0.f, 0.f);
        if (pos < 2000){
            sc = __uint_as_float((u32)(key >> 32));
            u32 idx = 0xFFFFFFFFu - (u32)(key & 0xFFFFFFFFull);
            bx = g_props[base + idx];
        }
        g_selscore[lv][pos] = sc;
        g_selbox[lv][pos]   = bx;
    }
}

// ---------------- NMS bitmask build (ballot, conflict-free, triangular skip) ----------------
__global__ void __launch_bounds__(256) k_masks(){
    int lv = blockIdx.x / 250;
    int rb = blockIdx.x % 250;
    __shared__ float4 bs[2048];
    int tid = threadIdx.x;
    for (int s = tid; s < 2048; s += 256) bs[s] = g_selbox[lv][s];
    __syncthreads();
    int row  = rb*8 + (tid >> 5);
    int lane = tid & 31;
    float4 bi = bs[row];
    float ai = (bi.z - bi.x) * (bi.w - bi.y);
    u64 word = 0ull;
    int rs = (row >= 31) ? ((row - 31) >> 5) : 0;   // rounds with any j > row
    for (int r = rs; r < 64; r++){
        int j = r*32 + lane;                         // lane-contiguous: no bank conflicts
        float4 bj = bs[j];
        float lx = fmaxf(bi.x, bj.x), ly = fmaxf(bi.y, bj.y);
        float rx = fminf(bi.z, bj.z), ry = fminf(bi.w, bj.w);
        float w = fmaxf(rx - lx, 0.f), h = fmaxf(ry - ly, 0.f);
        float inter = w * h;
        float aj = (bj.z - bj.x) * (bj.w - bj.y);
        float uni = fmaxf(ai + aj - inter, 1e-9f);
        bool pred = (j > row) && (inter > 0.7f * uni);
        u32 bal = __ballot_sync(0xffffffffu, pred);
        if (lane == (r >> 1))
            word |= (r & 1) ? ((u64)bal << 32) : (u64)bal;
    }
    g_masks[lv][row*32 + lane] = word;
}

// ---------------- serial greedy NMS: one warp per level, 16-deep prefetch ----------------
__global__ void __launch_bounds__(32) k_reduce(){
    int lv = blockIdx.x, t = threadIdx.x;
    u64 keep = 0ull;
#pragma unroll 4
    for (int bb = 0; bb < 64; bb++){
        int i = t*64 + bb;
        if (i < 2000 && g_selscore[lv][i] > 0.f) keep |= (1ull << bb);
    }
    u64 pf[16];
#pragma unroll
    for (int d = 0; d < 16; d++) pf[d] = g_masks[lv][d*32 + t];
    for (int ib = 0; ib < 2000; ib += 16){
#pragma unroll
        for (int d = 0; d < 16; d++){
            int i = ib + d;
            u64 m = pf[d];
            int nx = i + 16;
            pf[d] = (nx < 2000) ? g_masks[lv][nx*32 + t] : 0ull;
            u64 kw = __shfl_sync(0xffffffffu, keep, i >> 6);
            if ((kw >> (i & 63)) & 1ull) keep &= ~m;
        }
    }
    g_keepw[lv][t] = keep;
}

// ---------------- stable compaction: kept entries in score order, first 1000 ----------------
__global__ void __launch_bounds__(256) k_output(float* __restrict__ out){
    int lv = blockIdx.x, tid = threadIdx.x;
    __shared__ u64 kw[32];
    __shared__ u32 P[32];
    if (tid < 32){
        u64 w = g_keepw[lv][tid];
        kw[tid] = w;
        u32 c = __popcll(w);
        u32 inc = c;
#pragma unroll
        for (int off = 1; off < 32; off <<= 1){
            u32 v = __shfl_up_sync(0xffffffffu, inc, off);
            if (tid >= off) inc += v;
        }
        P[tid] = inc - c;   // exclusive word prefix
    }
    __syncthreads();
    for (int i = tid; i < 2000; i += 256){
        int w = i >> 6, bb = i & 63;
        u64 word = kw[w];
        if ((word >> bb) & 1ull){
            u32 rank = P[w] + (u32)__popcll(word & ((1ull << bb) - 1ull));
            if (rank < 1000){
                out[R_FS + lv*1000 + rank] = g_selscore[lv][i];
                ((float4*)(out + R_FP))[lv*1000 + rank] = g_selbox[lv][i];
            }
        }
    }
}

extern "C" void kernel_launch(void* const* d_in, const int* in_sizes, int n_in,
                              void* d_out, int out_size){
    const float* fpn0 = (const float*)d_in[0];
    const float* fpn1 = (const float*)d_in[1];
    const float* cw0  = (const float*)d_in[2];
    const float* cb0  = (const float*)d_in[3];
    const float* cw1  = (const float*)d_in[4];
    const float* cb1  = (const float*)d_in[5];
    const float* detw = (const float*)d_in[6];
    const float* detb = (const float*)d_in[7];
    const float* regw = (const float*)d_in[8];
    const float* regb = (const float*)d_in[9];
    float* out = (float*)d_out;

    k_init<<<40, 256>>>(out);
    k_fold<<<18, 256>>>(cw0, cw1, detw, regw);
    k_foldb<<<1, 32>>>(cb0, cb1, detw, detb, regw, regb);
    k_conv<<<353, 128>>>(fpn0, fpn1, out);
    k_hist<<<148, 256>>>(0);
    k_scan<<<2, 256>>>();
    k_hist<<<148, 256>>>(1);
    k_scan<<<2, 256>>>();
    k_build<<<148, 256>>>();
    for (int p = 3; p <= 7; p++)
        k_step<<<2, 256>>>(p);
    k_final<<<2, 256>>>();
    k_sortgather<<<2, 1024>>>();
    k_masks<<<500, 256>>>();
    k_reduce<<<2, 32>>>();
    k_output<<<2, 256>>>(out);
}

// round 17
// speedup vs baseline: 4.0747x; 1.2107x over previous
#include <cuda_runtime.h>
#include <math.h>

typedef unsigned long long u64;
typedef unsigned int u32;

// ---------------- problem constants ----------------
#define L0H 200
#define L0W 336
#define L1H 100
#define L1W 168
#define HW0 (L0H*L0W)      // 67200
#define HW1 (L1H*L1W)      // 16800
#define NPIX (HW0+HW1)     // 84000
#define N0 (3*HW0)         // 201600
#define N1 (3*HW1)         // 50400
#define NT (N0+N1)         // 252000
// output regions (floats), tuple order:
// anchors (NT,4) | obj (1,NT) | f_scores (2000) | f_props (2000,4) | deltas (1,NT,4)
#define R_OBJ   (NT*4)          // 1008000
#define R_FS    (R_OBJ+NT)      // 1260000
#define R_FP    (R_FS+2000)     // 1262000
#define R_DELTA (R_FP+8000)     // 1270000

#define CAND_CAP 131072
#define NSEL 2304               // approx-select margin (>=2000 final)
#define SORTN 4096

// ---------------- device scratch (static, no runtime alloc) ----------------
__device__ u64    g_wpk[2][2304][16];   // packed folded weights: dup-f32x2; [l= i*9+tap][o], o<15 (12 reg + 3 det approx)
__device__ double g_cwd2[2][3][256][9]; // exact fp64 det weights [a][i][tap] for refine
__device__ float  g_cb[2][12];          // folded reg bias
__device__ float  g_cba[2][3];          // folded det bias (approx fp32)
__device__ double g_cbd[2][3];          // folded det bias (fp64)
__device__ float  g_part[2][NPIX][16];  // conv partial sums per channel-split
__device__ float4 g_props[NT];          // decoded+clipped proposals
__device__ u64    g_keys[NT];           // (score_bits<<32)|(0xFFFFFFFF-idx): unique, stable tiebreak
__device__ u64    g_cand[2][CAND_CAP];  // radix candidate lists (keys >= prefix16<<48)
__device__ int    g_candcnt[2];
__device__ u64    g_selkeys[2][SORTN];
__device__ float4 g_selbox[2][2048];
__device__ float  g_selscore[2][2048];
__device__ u64    g_masks[2][2000*32];  // NMS suppression bitmatrix (row i: bits j>i with iou>0.7)
__device__ u64    g_keepw[2][32];
__device__ u64    g_prefix[2];
__device__ int    g_krem[2];
__device__ u32    g_hist[2][256];

// ---------------- f32x2 helpers ----------------
__device__ __forceinline__ u64 pk2(float lo, float hi){
    u64 v; asm("mov.b64 %0,{%1,%2};" : "=l"(v) : "f"(lo), "f"(hi)); return v;
}
__device__ __forceinline__ void upk2(u64 v, float& lo, float& hi){
    asm("mov.b64 {%0,%1},%2;" : "=f"(lo), "=f"(hi) : "l"(v));
}
__device__ __forceinline__ u64 ff2(u64 a, u64 b, u64 c){
    u64 d; asm("fma.rn.f32x2 %0,%1,%2,%3;" : "=l"(d) : "l"(a), "l"(b), "l"(c)); return d;
}

// ---------------- per-call init ----------------
__global__ void k_init(float* __restrict__ out){
    int t = blockIdx.x*blockDim.x + threadIdx.x;
    if (t < 2){ g_prefix[t] = 0ull; g_krem[t] = NSEL; g_candcnt[t] = 0; }
    if (t < 512) g_hist[t>>8][t&255] = 0u;
    if (t < 2*SORTN) ((u64*)g_selkeys)[t] = 0ull;
    if (t < 10000) out[R_FS + t] = 0.f;   // zero f_scores + f_props regions
}

// ---------------- fold weights: cw[lv][l][o] = sum_c head_w[o,c]*conv_w[c][l] ----------------
// reg channels fp32; det channels folded in fp64 (exact copy kept for refine, fp32 approx in pack).
__global__ void __launch_bounds__(256) k_fold(const float* __restrict__ w30,
                                              const float* __restrict__ w31,
                                              const float* __restrict__ detw,
                                              const float* __restrict__ regw){
    __shared__ float  hwr[12*256];
    __shared__ double hwd[3*256];
    int tid = threadIdx.x;
    for (int s = tid; s < 12*256; s += 256){
        int o = s >> 8, c = s & 255;
        hwr[s] = regw[o*256 + c];
    }
    for (int s = tid; s < 3*256; s += 256){
        int o = s >> 8, c = s & 255;
        hwd[s] = (double)detw[o*256 + c];
    }
    __syncthreads();
    int lin = blockIdx.x*256 + tid;          // 0..4607
    int lv  = (lin >= 2304);
    int l   = lv ? (lin - 2304) : lin;       // 0..2303 = i*9 + tap
    const float* w3 = lv ? w31 : w30;
    float  fa[12];
    double da[3];
#pragma unroll
    for (int o = 0; o < 12; o++) fa[o] = 0.f;
#pragma unroll
    for (int a = 0; a < 3; a++) da[a] = 0.0;
    for (int c = 0; c < 256; c++){
        float x = w3[c*2304 + l];
        double xd = (double)x;
#pragma unroll
        for (int a = 0; a < 3; a++) da[a] += hwd[(a<<8) + c] * xd;
#pragma unroll
        for (int o = 0; o < 12; o++) fa[o] += hwr[(o<<8) + c] * x;
    }
#pragma unroll
    for (int o = 0; o < 12; o++) g_wpk[lv][l][o] = pk2(fa[o], fa[o]);
#pragma unroll
    for (int a = 0; a < 3; a++){
        float w = (float)da[a];
        g_wpk[lv][l][12+a] = pk2(w, w);
    }
    g_wpk[lv][l][15] = 0ull;
    int i = l / 9, tap = l % 9;
#pragma unroll
    for (int a = 0; a < 3; a++) g_cwd2[lv][a][i][tap] = da[a];
}

__global__ void k_foldb(const float* __restrict__ cb0, const float* __restrict__ cb1,
                        const float* __restrict__ detw, const float* __restrict__ detb,
                        const float* __restrict__ regw, const float* __restrict__ regb){
    int t = threadIdx.x;
    if (t >= 32) return;
    int lv = t / 16, o = t % 16;
    const float* cb = lv ? cb1 : cb0;
    if (o < 3){
        double s = (double)detb[o];
        for (int c = 0; c < 256; c++) s += (double)detw[o*256 + c] * (double)cb[c];
        g_cbd[lv][o] = s;
        g_cba[lv][o] = (float)s;
    } else if (o < 15){
        int ro = o - 3;
        float s = regb[ro];
        for (int c = 0; c < 256; c++) s += regw[ro*256 + c] * cb[c];
        g_cb[lv][ro] = s;
    }
}

// ---------------- conv3x3 (folded, pure fp32), channel-split x2 ----------------
// tile 8H x 32W, 128 threads, 2 px/thread; 706 blocks -> ~19 warps/SM.
// writes partial sums (no bias) to g_part[split].
__global__ void __launch_bounds__(128) k_conv(const float* __restrict__ x0,
                                              const float* __restrict__ x1){
    __shared__ float xs[8][10][34];
    __shared__ u64   wsa[1152];        // 8 ic * 9 taps * 16 slots
    int b = blockIdx.x;
    int split = b & 1;
    int tile  = b >> 1;
    int lv, H, W, pixbase, tx, ty; const float* xin;
    if (tile < 275){ lv = 0; tx = tile % 11; ty = tile / 11; H = L0H; W = L0W; xin = x0; pixbase = 0; }
    else { int c = tile - 275; lv = 1; tx = c % 6; ty = c / 6; H = L1H; W = L1W; xin = x1; pixbase = HW0; }
    int HW = H * W;
    int X0 = tx * 32, Y0 = ty * 8;
    int tid = threadIdx.x;
    int wcol = tid & 31, r0 = (tid >> 5) * 2;

    u64 acc[15];
#pragma unroll
    for (int o = 0; o < 15; o++) acc[o] = 0ull;

    int cc0 = split * 128;
    for (int cc = cc0; cc < cc0 + 128; cc += 8){
        __syncthreads();
        for (int s = tid; s < 8*10*34; s += 128){
            int ic = s / 340; int rm = s - ic*340; int r = rm / 34; int c2 = rm - r*34;
            int gy = Y0 - 1 + r, gx = X0 - 1 + c2;
            float v = 0.f;
            if ((unsigned)gy < (unsigned)H && (unsigned)gx < (unsigned)W)
                v = xin[(cc+ic)*HW + gy*W + gx];
            xs[ic][r][c2] = v;
        }
        {   // stage packed weights: contiguous 1152 u64 starting at l = cc*9
            const ulonglong2* src = (const ulonglong2*)&g_wpk[lv][cc*9][0];
            ulonglong2* dst = (ulonglong2*)wsa;
            for (int s = tid; s < 576; s += 128) dst[s] = src[s];
        }
        __syncthreads();
#pragma unroll 1
        for (int ic = 0; ic < 8; ic++){
            float xc[3][4];
#pragma unroll
            for (int kx = 0; kx < 3; kx++)
#pragma unroll
                for (int m = 0; m < 4; m++)
                    xc[kx][m] = xs[ic][r0 + m][wcol + kx];
#pragma unroll
            for (int ky = 0; ky < 3; ky++){
#pragma unroll
                for (int kx = 0; kx < 3; kx++){
                    u64 xv = pk2(xc[kx][ky], xc[kx][ky+1]);
                    const u64* wp = &wsa[(ic*9 + ky*3 + kx)*16];
#pragma unroll
                    for (int o = 0; o < 15; o++)
                        acc[o] = ff2(wp[o], xv, acc[o]);
                }
            }
        }
    }

#pragma unroll
    for (int p = 0; p < 2; p++){
        int gy = Y0 + r0 + p, gx = X0 + wcol;
        if (gy >= H || gx >= W) continue;
        int gpix = pixbase + gy*W + gx;
        float v[16];
#pragma unroll
        for (int o = 0; o < 15; o++){
            float lo, hi; upk2(acc[o], lo, hi);
            v[o] = p ? hi : lo;
        }
        v[15] = 0.f;
        float4* pp = (float4*)&g_part[split][gpix][0];
        pp[0] = make_float4(v[0], v[1], v[2],  v[3]);
        pp[1] = make_float4(v[4], v[5], v[6],  v[7]);
        pp[2] = make_float4(v[8], v[9], v[10], v[11]);
        pp[3] = make_float4(v[12], v[13], v[14], v[15]);
    }
}

// ---------------- combine partials + epilogue: sigmoid/anchors/decode/keys ----------------
__global__ void __launch_bounds__(128) k_combine(float* __restrict__ out){
    int t = blockIdx.x*blockDim.x + threadIdx.x;
    if (t >= NPIX) return;
    int lv = (t >= HW0);
    int pix = t - (lv ? HW0 : 0);
    int H = lv ? L1H : L0H, W = lv ? L1W : L0W;
    int HW = H * W;
    int lvbase = lv ? N0 : 0;
    int gy = pix / W, gx = pix - gy*W;

    const float4* p0 = (const float4*)&g_part[0][t][0];
    const float4* p1 = (const float4*)&g_part[1][t][0];
    float v[16];
#pragma unroll
    for (int k = 0; k < 4; k++){
        float4 a = p0[k], b2 = p1[k];
        v[4*k+0] = a.x + b2.x; v[4*k+1] = a.y + b2.y;
        v[4*k+2] = a.z + b2.z; v[4*k+3] = a.w + b2.w;
    }
    float rv[12];
#pragma unroll
    for (int o = 0; o < 12; o++) rv[o] = v[o] + g_cb[lv][o];
    float dlog[3];
#pragma unroll
    for (int a = 0; a < 3; a++) dlog[a] = v[12+a] + g_cba[lv][a];

    float scale = lv ? 8.f : 4.f;
    float sz    = lv ? 64.f : 32.f;
    float cx = (gx + 0.5f) * scale, cy = (gy + 0.5f) * scale;
#pragma unroll
    for (int a = 0; a < 3; a++){
        float score = 1.f / (1.f + expf(-dlog[a]));
        int idx  = a*HW + pix;
        int gidx = lvbase + idx;
        out[R_OBJ + gidx] = score;
        g_keys[gidx] = ((u64)__float_as_uint(score) << 32) | (u64)(0xFFFFFFFFu - (u32)idx);

        float r  = (a == 0) ? 0.5f : ((a == 1) ? 1.f : 2.f);
        float sq = sqrtf(r);
        float ahh = sz * sq, aww = sz / sq;
        float x1 = cx - aww*0.5f, x2 = cx + aww*0.5f;
        float y1 = cy - ahh*0.5f, y2 = cy + ahh*0.5f;
        x1 = fminf(fmaxf(x1, 0.f), 1344.f); x2 = fminf(fmaxf(x2, 0.f), 1344.f);
        y1 = fminf(fmaxf(y1, 0.f),  800.f); y2 = fminf(fmaxf(y2, 0.f),  800.f);
        ((float4*)out)[gidx] = make_float4(x1, y1, x2, y2);   // anchors at region 0

        float dx = rv[a], dy = rv[3+a], dw = rv[6+a], dh = rv[9+a];
        ((float4*)(out + R_DELTA))[gidx] = make_float4(dx, dy, dw, dh);

        float aw2 = x2 - x1, ah2 = y2 - y1;
        float acx = y1 + aw2*0.5f;   // reference's swap quirk (faithful)
        float acy = x1 + ah2*0.5f;
        float px = acx + dx*aw2, py = acy + dy*ah2;
        float pw = aw2 * expf(dw), ph = ah2 * expf(dh);
        float bx1 = px - pw*0.5f, by1 = py - ph*0.5f;
        float bx2 = px + pw*0.5f, by2 = py + ph*0.5f;
        bx1 = fminf(fmaxf(bx1, 0.f), 1344.f); bx2 = fminf(fmaxf(bx2, 0.f), 1344.f);
        by1 = fminf(fmaxf(by1, 0.f),  800.f); by2 = fminf(fmaxf(by2, 0.f),  800.f);
        g_props[gidx] = make_float4(bx1, by1, bx2, by2);
    }
}

// ---------------- radix-select: approx top-NSEL per level ----------------
__global__ void k_hist(int pass){
    __shared__ u32 h[512];
    for (int i = threadIdx.x; i < 512; i += blockDim.x) h[i] = 0u;
    __syncthreads();
    int shift = 56 - 8*pass;
    u64 p0 = g_prefix[0], p1 = g_prefix[1];
    for (int i = blockIdx.x*blockDim.x + threadIdx.x; i < NT; i += gridDim.x*blockDim.x){
        int lv = (i >= N0);
        u64 key = g_keys[i];
        bool ok = (pass == 0) || ((key >> (shift + 8)) == (lv ? p1 : p0));
        if (ok) atomicAdd(&h[(lv << 8) | (u32)((key >> shift) & 255)], 1u);
    }
    __syncthreads();
    for (int i = threadIdx.x; i < 512; i += blockDim.x){
        u32 v = h[i];
        if (v) atomicAdd(&g_hist[i>>8][i&255], v);
    }
}

__global__ void k_scan(){   // grid 2 (level): pick digit of the NSEL-th-largest key
    int lv = blockIdx.x, d = threadIdx.x;
    __shared__ u32 s[256];
    s[d] = g_hist[lv][d];
    __syncthreads();
    for (int off = 1; off < 256; off <<= 1){   // inclusive suffix sum
        u32 v = (d + off < 256) ? s[d + off] : 0u;
        __syncthreads();
        s[d] += v;
        __syncthreads();
    }
    u32 krem  = (u32)g_krem[lv];
    u32 suf   = s[d];
    u32 above = (d < 255) ? s[d+1] : 0u;
    if (above < krem && krem <= suf){
        g_prefix[lv] = (g_prefix[lv] << 8) | (u64)(u32)d;
        g_krem[lv]   = (int)(krem - above);
    }
    g_hist[lv][d] = 0u;
}

__global__ void k_build(){
    __shared__ u32 h[512];
    for (int i = threadIdx.x; i < 512; i += blockDim.x) h[i] = 0u;
    __syncthreads();
    u64 p0 = g_prefix[0], p1 = g_prefix[1];
    for (int i = blockIdx.x*blockDim.x + threadIdx.x; i < NT; i += gridDim.x*blockDim.x){
        int lv = (i >= N0);
        u64 key = g_keys[i];
        u64 top2 = key >> 48;
        u64 pref = lv ? p1 : p0;
        if (top2 >= pref){
            int p = atomicAdd(&g_candcnt[lv], 1);
            if (p < CAND_CAP) g_cand[lv][p] = key;
            if (top2 == pref)
                atomicAdd(&h[(lv << 8) | (u32)((key >> 40) & 255)], 1u);
        }
    }
    __syncthreads();
    for (int i = threadIdx.x; i < 512; i += blockDim.x){
        u32 v = h[i];
        if (v) atomicAdd(&g_hist[i>>8][i&255], v);
    }
}

__global__ void __launch_bounds__(256) k_step(int pass){
    int lv = blockIdx.x, d = threadIdx.x;
    __shared__ u32 s[256];
    __shared__ u32 h[256];
    __shared__ u64 spref;
    s[d] = g_hist[lv][d];
    h[d] = 0u;
    __syncthreads();
    for (int off = 1; off < 256; off <<= 1){
        u32 v = (d + off < 256) ? s[d + off] : 0u;
        __syncthreads();
        s[d] += v;
        __syncthreads();
    }
    u32 krem  = (u32)g_krem[lv];
    u32 suf   = s[d];
    u32 above = (d < 255) ? s[d+1] : 0u;
    if (above < krem && krem <= suf){
        u64 np = (g_prefix[lv] << 8) | (u64)(u32)d;
        g_prefix[lv] = np;
        g_krem[lv]   = (int)(krem - above);
        spref = np;
    }
    __syncthreads();
    u64 pref = spref;
    int shift = 56 - 8*pass;
    int n = g_candcnt[lv]; if (n > CAND_CAP) n = CAND_CAP;
    for (int i = d; i < n; i += 256){
        u64 key = g_cand[lv][i];
        if ((key >> (shift + 8)) == pref)
            atomicAdd(&h[(u32)((key >> shift) & 255)], 1u);
    }
    __syncthreads();
    g_hist[lv][d] = h[d];
}

__global__ void __launch_bounds__(256) k_final(){
    int lv = blockIdx.x, d = threadIdx.x;
    __shared__ u32 s[256];
    __shared__ u64 sthr;
    __shared__ int scnt;
    s[d] = g_hist[lv][d];
    if (d == 0) scnt = 0;
    __syncthreads();
    for (int off = 1; off < 256; off <<= 1){
        u32 v = (d + off < 256) ? s[d + off] : 0u;
        __syncthreads();
        s[d] += v;
        __syncthreads();
    }
    u32 krem  = (u32)g_krem[lv];
    u32 suf   = s[d];
    u32 above = (d < 255) ? s[d+1] : 0u;
    if (above < krem && krem <= suf)
        sthr = (g_prefix[lv] << 8) | (u64)(u32)d;
    __syncthreads();
    u64 thr = sthr;
    int n = g_candcnt[lv]; if (n > CAND_CAP) n = CAND_CAP;
    for (int i = d; i < n; i += 256){
        u64 key = g_cand[lv][i];
        if (key >= thr){                 // unique keys -> exactly NSEL pass
            int p = atomicAdd(&scnt, 1);
            if (p < SORTN) g_selkeys[lv][p] = key;
        }
    }
}

// ---------------- exact refine: recompute selected logits in fp64, rebuild keys ----------------
__global__ void __launch_bounds__(256) k_refine(const float* __restrict__ x0,
                                                const float* __restrict__ x1){
    int gw = blockIdx.x * 8 + (threadIdx.x >> 5);   // global warp = candidate
    int lane = threadIdx.x & 31;
    int lv = (gw >= NSEL);
    int slot = gw - (lv ? NSEL : 0);
    u64 key = g_selkeys[lv][slot];
    u32 idx = 0xFFFFFFFFu - (u32)key;
    int H = lv ? L1H : L0H, W = lv ? L1W : L0W;
    int HW = H * W;
    int a = idx / HW, pix = idx - a*HW;
    int y = pix / W, x = pix - y*W;
    const float* xin = lv ? x1 : x0;
    double s = 0.0;
    for (int c = lane; c < 256; c += 32){
        const double* wp = &g_cwd2[lv][a][c][0];
        const float* xp = xin + c*HW;
#pragma unroll
        for (int ky = 0; ky < 3; ky++){
            int gy = y + ky - 1;
#pragma unroll
            for (int kx = 0; kx < 3; kx++){
                int gx = x + kx - 1;
                float xv = 0.f;
                if ((unsigned)gy < (unsigned)H && (unsigned)gx < (unsigned)W)
                    xv = xp[gy*W + gx];
                s += wp[ky*3+kx] * (double)xv;
            }
        }
    }
#pragma unroll
    for (int off = 16; off > 0; off >>= 1)
        s += __shfl_down_sync(0xffffffffu, s, off);
    if (lane == 0){
        s += g_cbd[lv][a];
        float lg = (float)s;
        float score = 1.f / (1.f + expf(-lg));
        g_selkeys[lv][slot] = ((u64)__float_as_uint(score) << 32) | (u64)(0xFFFFFFFFu - idx);
    }
}

// ---------------- bitonic sort 4096 (descending) + gather top-2000 ----------------
__global__ void __launch_bounds__(1024) k_sort4k(){
    int lv = blockIdx.x, t = threadIdx.x;
    __shared__ u64 sk[SORTN];
#pragma unroll
    for (int v = 0; v < 4; v++) sk[t + v*1024] = g_selkeys[lv][t + v*1024];
    __syncthreads();
    for (int k = 2; k <= SORTN; k <<= 1){
        for (int j = k >> 1; j > 0; j >>= 1){
#pragma unroll
            for (int v = 0; v < 2; v++){
                int t2 = t + v*1024;
                int i1 = ((t2 & ~(j-1)) << 1) | (t2 & (j-1));
                int i2 = i1 + j;
                u64 a = sk[i1], b = sk[i2];
                bool up = ((i1 & k) == 0);
                if (up ? (a < b) : (a > b)){ sk[i1] = b; sk[i2] = a; }
            }
            __syncthreads();
        }
    }
    int base = lv ? N0 : 0;
    for (int pos = t; pos < 2048; pos += 1024){
        u64 key = sk[pos];
        float sc = 0.f; float4 bx = make_float4(0.f, 0.f, 0.f, 0.f);
        if (pos < 2000){
            sc = __uint_as_float((u32)(key >> 32));
            u32 idx = 0xFFFFFFFFu - (u32)(key & 0xFFFFFFFFull);
            bx = g_props[base + idx];
        }
        g_selscore[lv][pos] = sc;
        g_selbox[lv][pos]   = bx;
    }
}

// ---------------- NMS bitmask build (ballot, conflict-free, triangular skip) ----------------
__global__ void __launch_bounds__(256) k_masks(){
    int lv = blockIdx.x / 250;
    int rb = blockIdx.x % 250;
    __shared__ float4 bs[2048];
    int tid = threadIdx.x;
    for (int s = tid; s < 2048; s += 256) bs[s] = g_selbox[lv][s];
    __syncthreads();
    int row  = rb*8 + (tid >> 5);
    int lane = tid & 31;
    float4 bi = bs[row];
    float ai = (bi.z - bi.x) * (bi.w - bi.y);
    u64 word = 0ull;
    int rs = (row >= 31) ? ((row - 31) >> 5) : 0;   // rounds with any j > row
    for (int r = rs; r < 64; r++){
        int j = r*32 + lane;                         // lane-contiguous: no bank conflicts
        float4 bj = bs[j];
        float lx = fmaxf(bi.x, bj.x), ly = fmaxf(bi.y, bj.y);
        float rx = fminf(bi.z, bj.z), ry = fminf(bi.w, bj.w);
        float w = fmaxf(rx - lx, 0.f), h = fmaxf(ry - ly, 0.f);
        float inter = w * h;
        float aj = (bj.z - bj.x) * (bj.w - bj.y);
        float uni = fmaxf(ai + aj - inter, 1e-9f);
        bool pred = (j > row) && (inter > 0.7f * uni);
        u32 bal = __ballot_sync(0xffffffffu, pred);
        if (lane == (r >> 1))
            word |= (r & 1) ? ((u64)bal << 32) : (u64)bal;
    }
    g_masks[lv][row*32 + lane] = word;
}

// ---------------- serial greedy NMS: one warp per level, 16-deep prefetch ----------------
__global__ void __launch_bounds__(32) k_reduce(){
    int lv = blockIdx.x, t = threadIdx.x;
    u64 keep = 0ull;
#pragma unroll 4
    for (int bb = 0; bb < 64; bb++){
        int i = t*64 + bb;
        if (i < 2000 && g_selscore[lv][i] > 0.f) keep |= (1ull << bb);
    }
    u64 pf[16];
#pragma unroll
    for (int d = 0; d < 16; d++) pf[d] = g_masks[lv][d*32 + t];
    for (int ib = 0; ib < 2000; ib += 16){
#pragma unroll
        for (int d = 0; d < 16; d++){
            int i = ib + d;
            u64 m = pf[d];
            int nx = i + 16;
            pf[d] = (nx < 2000) ? g_masks[lv][nx*32 + t] : 0ull;
            u64 kw = __shfl_sync(0xffffffffu, keep, i >> 6);
            if ((kw >> (i & 63)) & 1ull) keep &= ~m;
        }
    }
    g_keepw[lv][t] = keep;
}

// ---------------- stable compaction: kept entries in score order, first 1000 ----------------
__global__ void __launch_bounds__(256) k_output(float* __restrict__ out){
    int lv = blockIdx.x, tid = threadIdx.x;
    __shared__ u64 kw[32];
    __shared__ u32 P[32];
    if (tid < 32){
        u64 w = g_keepw[lv][tid];
        kw[tid] = w;
        u32 c = __popcll(w);
        u32 inc = c;
#pragma unroll
        for (int off = 1; off < 32; off <<= 1){
            u32 v = __shfl_up_sync(0xffffffffu, inc, off);
            if (tid >= off) inc += v;
        }
        P[tid] = inc - c;   // exclusive word prefix
    }
    __syncthreads();
    for (int i = tid; i < 2000; i += 256){
        int w = i >> 6, bb = i & 63;
        u64 word = kw[w];
        if ((word >> bb) & 1ull){
            u32 rank = P[w] + (u32)__popcll(word & ((1ull << bb) - 1ull));
            if (rank < 1000){
                out[R_FS + lv*1000 + rank] = g_selscore[lv][i];
                ((float4*)(out + R_FP))[lv*1000 + rank] = g_selbox[lv][i];
            }
        }
    }
}

extern "C" void kernel_launch(void* const* d_in, const int* in_sizes, int n_in,
                              void* d_out, int out_size){
    const float* fpn0 = (const float*)d_in[0];
    const float* fpn1 = (const float*)d_in[1];
    const float* cw0  = (const float*)d_in[2];
    const float* cb0  = (const float*)d_in[3];
    const float* cw1  = (const float*)d_in[4];
    const float* cb1  = (const float*)d_in[5];
    const float* detw = (const float*)d_in[6];
    const float* detb = (const float*)d_in[7];
    const float* regw = (const float*)d_in[8];
    const float* regb = (const float*)d_in[9];
    float* out = (float*)d_out;

    k_init<<<40, 256>>>(out);
    k_fold<<<18, 256>>>(cw0, cw1, detw, regw);
    k_foldb<<<1, 32>>>(cb0, cb1, detw, detb, regw, regb);
    k_conv<<<706, 128>>>(fpn0, fpn1);
    k_combine<<<657, 128>>>(out);
    k_hist<<<148, 256>>>(0);
    k_scan<<<2, 256>>>();
    k_hist<<<148, 256>>>(1);
    k_scan<<<2, 256>>>();
    k_build<<<148, 256>>>();
    for (int p = 3; p <= 7; p++)
        k_step<<<2, 256>>>(p);
    k_final<<<2, 256>>>();
    k_refine<<<576, 256>>>(fpn0, fpn1);
    k_sort4k<<<2, 1024>>>();
    k_masks<<<500, 256>>>();
    k_reduce<<<2, 32>>>();
    k_output<<<2, 256>>>(out);
}